// round 1
// baseline (speedup 1.0000x reference)
#include <cuda_runtime.h>
#include <math.h>

#define BB 32
#define CC 512
#define QQ 128
#define DD 768
#define OD (4*DD)
#define NEGV (-1e30f)

// ---------------- scratch (static device arrays; no allocs) ----------------
__device__ float g_S[BB*CC*QQ];        // similarity, later overwritten with dist
__device__ float g_cq1[BB*CC];
__device__ float g_qq2[BB*QQ];
__device__ float g_pmax[BB*4*QQ];
__device__ float g_psum[BB*4*QQ];
__device__ float g_colmax[BB*QQ];
__device__ float g_colrsum[BB*QQ];
__device__ float g_Smax[BB*CC];
__device__ float g_cdd[BB*CC];
__device__ float g_cdash[BB*DD];

// ---------------- packed f32x2 helpers ----------------
__device__ __forceinline__ unsigned long long pack2(float lo, float hi){
    unsigned long long r;
    asm("mov.b64 %0, {%1, %2};" : "=l"(r)
        : "r"(__float_as_uint(lo)), "r"(__float_as_uint(hi)));
    return r;
}
__device__ __forceinline__ void unpack2(unsigned long long v, float& lo, float& hi){
    unsigned int a, b;
    asm("mov.b64 {%0, %1}, %2;" : "=r"(a), "=r"(b) : "l"(v));
    lo = __uint_as_float(a); hi = __uint_as_float(b);
}
__device__ __forceinline__ void ffma2(unsigned long long& d,
                                      unsigned long long a, unsigned long long b){
    asm("fma.rn.f32x2 %0, %1, %2, %0;" : "+l"(d) : "l"(a), "l"(b));
}

// ---------------- K0: row dots cont·w1, ques·w2 ----------------
__global__ void k_rowdots(const float* __restrict__ cont,
                          const float* __restrict__ ques,
                          const float* __restrict__ SW){
    int gw   = (blockIdx.x * blockDim.x + threadIdx.x) >> 5;
    int lane = threadIdx.x & 31;
    if (gw < BB*CC){
        const float* row = cont + (size_t)gw * DD;
        float s = 0.f;
        #pragma unroll 4
        for (int i = lane; i < DD; i += 32) s += row[i] * SW[i];
        #pragma unroll
        for (int o = 16; o; o >>= 1) s += __shfl_xor_sync(0xffffffffu, s, o);
        if (!lane) g_cq1[gw] = s;
    } else if (gw < BB*CC + BB*QQ){
        int r = gw - BB*CC;
        const float* row = ques + (size_t)r * DD;
        float s = 0.f;
        #pragma unroll 4
        for (int i = lane; i < DD; i += 32) s += row[i] * SW[DD + i];
        #pragma unroll
        for (int o = 16; o; o >>= 1) s += __shfl_xor_sync(0xffffffffu, s, o);
        if (!lane) g_qq2[r] = s;
    }
}

// ---------------- K1: GEMM1 -> S, Smax ----------------
__global__ __launch_bounds__(256, 2)
void k_gemm1(const float* __restrict__ cont,
             const float* __restrict__ ques,
             const float* __restrict__ SW){
    __shared__ unsigned long long As2[16][128];   // dup-packed A [k][c]
    __shared__ float Bs[16][128];                 // (w3*ques) [k][q]
    __shared__ float s_w3[DD];

    int b  = blockIdx.y;
    int c0 = blockIdx.x * 128;
    int tid = threadIdx.x, tx = tid & 15, ty = tid >> 4;

    for (int i = tid; i < DD; i += 256) s_w3[i] = SW[2*DD + i];
    __syncthreads();

    const float* Ag = cont + ((size_t)b*CC + c0) * DD;
    const float* Bg = ques + (size_t)b*QQ*DD;

    unsigned long long acc[8][4];
    #pragma unroll
    for (int i = 0; i < 8; i++)
        #pragma unroll
        for (int j = 0; j < 4; j++) acc[i][j] = 0ull;

    for (int k0 = 0; k0 < DD; k0 += 16){
        #pragma unroll
        for (int u = 0; u < 2; u++){
            int f = tid + u*256;
            int r = f >> 2, kk = (f & 3) << 2;
            float4 v = *(const float4*)(Ag + (size_t)r*DD + k0 + kk);
            As2[kk+0][r] = pack2(v.x, v.x);
            As2[kk+1][r] = pack2(v.y, v.y);
            As2[kk+2][r] = pack2(v.z, v.z);
            As2[kk+3][r] = pack2(v.w, v.w);
            float4 w = *(const float4*)(Bg + (size_t)r*DD + k0 + kk);  // r = q
            Bs[kk+0][r] = w.x * s_w3[k0+kk+0];
            Bs[kk+1][r] = w.y * s_w3[k0+kk+1];
            Bs[kk+2][r] = w.z * s_w3[k0+kk+2];
            Bs[kk+3][r] = w.w * s_w3[k0+kk+3];
        }
        __syncthreads();
        #pragma unroll
        for (int k = 0; k < 16; k++){
            unsigned long long a2[8];
            #pragma unroll
            for (int i = 0; i < 8; i++) a2[i] = As2[k][ty*8 + i];
            const ulonglong2* bp = reinterpret_cast<const ulonglong2*>(&Bs[k][tx*8]);
            ulonglong2 p0 = bp[0], p1 = bp[1];
            unsigned long long bf[4] = {p0.x, p0.y, p1.x, p1.y};
            #pragma unroll
            for (int i = 0; i < 8; i++)
                #pragma unroll
                for (int j = 0; j < 4; j++) ffma2(acc[i][j], a2[i], bf[j]);
        }
        __syncthreads();
    }

    // epilogue: add rank-1 terms, write S, compute row max
    float qv[8];
    #pragma unroll
    for (int j = 0; j < 8; j++) qv[j] = g_qq2[b*QQ + tx*8 + j];
    #pragma unroll
    for (int i = 0; i < 8; i++){
        int c = c0 + ty*8 + i;
        float cq = g_cq1[b*CC + c];
        float s[8];
        #pragma unroll
        for (int j = 0; j < 4; j++) unpack2(acc[i][j], s[2*j], s[2*j+1]);
        float rmax = -INFINITY;
        #pragma unroll
        for (int j = 0; j < 8; j++){ s[j] += cq + qv[j]; rmax = fmaxf(rmax, s[j]); }
        float* So = g_S + ((size_t)b*CC + c)*QQ + tx*8;
        *(float4*)So     = make_float4(s[0], s[1], s[2], s[3]);
        *(float4*)(So+4) = make_float4(s[4], s[5], s[6], s[7]);
        #pragma unroll
        for (int o = 8; o; o >>= 1) rmax = fmaxf(rmax, __shfl_xor_sync(0xffffffffu, rmax, o));
        if (tx == 0) g_Smax[b*CC + c] = rmax;
    }
}

// ---------------- K2a: partial column softmax stats over c-chunks ----------------
__global__ void k_colpart(const int* __restrict__ qmask){
    int b = blockIdx.y, ch = blockIdx.x;
    int q = threadIdx.x;                 // 128
    float madd = (1.0f - (float)qmask[b*QQ + q]) * NEGV;
    const float* Sp = g_S + ((size_t)b*CC + ch*128)*QQ + q;
    float m = -INFINITY, sum = 0.f;
    #pragma unroll 4
    for (int c = 0; c < 128; c++){
        float v  = Sp[(size_t)c*QQ] + madd;   // fp32 absorption matches reference
        float mn = fmaxf(m, v);
        sum = sum * expf(m - mn) + expf(v - mn);
        m = mn;
    }
    g_pmax[(b*4 + ch)*QQ + q] = m;
    g_psum[(b*4 + ch)*QQ + q] = sum;
}

// ---------------- K2b: combine partials ----------------
__global__ void k_colfinal(){
    int b = blockIdx.x, q = threadIdx.x;
    float m = -INFINITY;
    #pragma unroll
    for (int ch = 0; ch < 4; ch++) m = fmaxf(m, g_pmax[(b*4+ch)*QQ + q]);
    float sum = 0.f;
    #pragma unroll
    for (int ch = 0; ch < 4; ch++)
        sum += g_psum[(b*4+ch)*QQ + q] * expf(g_pmax[(b*4+ch)*QQ + q] - m);
    g_colmax[b*QQ + q]  = m;
    g_colrsum[b*QQ + q] = 1.0f / sum;
}

// ---------------- K2c: S -> dist in place ----------------
__global__ void k_dist(const int* __restrict__ qmask){
    int idx = blockIdx.x * 256 + threadIdx.x;          // over float4s
    int b  = idx >> 14;                                // CC*QQ/4 = 16384
    int q4 = (idx & 31) << 2;
    float4 s = ((const float4*)g_S)[idx];
    float md[4], cm[4], cr[4];
    #pragma unroll
    for (int t = 0; t < 4; t++){
        int q = q4 + t;
        md[t] = (1.0f - (float)qmask[b*QQ + q]) * NEGV;
        cm[t] = g_colmax[b*QQ + q];
        cr[t] = g_colrsum[b*QQ + q];
    }
    float4 r;
    r.x = expf((s.x + md[0]) - cm[0]) * cr[0];
    r.y = expf((s.y + md[1]) - cm[1]) * cr[1];
    r.z = expf((s.z + md[2]) - cm[2]) * cr[2];
    r.w = expf((s.w + md[3]) - cm[3]) * cr[3];
    ((float4*)g_S)[idx] = r;
}

// ---------------- K3a: c_dash_dist (softmax over c of Smax + cmask) ----------------
__global__ void k_cdd(const int* __restrict__ cmask){
    __shared__ float red[CC];
    int b = blockIdx.x, c = threadIdx.x;      // 512 threads
    float v = g_Smax[b*CC + c] + (1.0f - (float)cmask[b*CC + c]) * NEGV;
    red[c] = v; __syncthreads();
    for (int s = 256; s; s >>= 1){
        if (c < s) red[c] = fmaxf(red[c], red[c + s]);
        __syncthreads();
    }
    float mx = red[0]; __syncthreads();
    float e = expf(v - mx);
    red[c] = e; __syncthreads();
    for (int s = 256; s; s >>= 1){
        if (c < s) red[c] += red[c + s];
        __syncthreads();
    }
    g_cdd[b*CC + c] = e / red[0];
}

// ---------------- K3b: c_dash[b,d] = sum_c cdd * cont ----------------
__global__ void k_cdash(const float* __restrict__ cont){
    __shared__ float sd[CC];
    int b = blockIdx.y;
    int d = blockIdx.x * 128 + threadIdx.x;
    for (int i = threadIdx.x; i < CC; i += 128) sd[i] = g_cdd[b*CC + i];
    __syncthreads();
    float acc = 0.f;
    #pragma unroll 4
    for (int c = 0; c < CC; c++)
        acc += sd[c] * cont[((size_t)b*CC + c)*DD + d];
    g_cdash[b*DD + d] = acc;
}

// ---------------- K4: GEMM2 (dist x ques) + fused 4-segment output ----------------
__global__ __launch_bounds__(256, 2)
void k_gemm2(const float* __restrict__ cont,
             const float* __restrict__ ques,
             float* __restrict__ out){
    __shared__ unsigned long long As2[16][128];   // dup-packed dist [q][c]
    __shared__ float Bs[16][128];                 // ques [q][d]

    int b  = blockIdx.z;
    int c0 = blockIdx.y * 128;
    int d0 = blockIdx.x * 128;
    int tid = threadIdx.x, tx = tid & 15, ty = tid >> 4;

    const float* Sg = g_S + ((size_t)b*CC + c0)*QQ;
    const float* Bg = ques + (size_t)b*QQ*DD + d0;

    unsigned long long acc[8][4];
    #pragma unroll
    for (int i = 0; i < 8; i++)
        #pragma unroll
        for (int j = 0; j < 4; j++) acc[i][j] = 0ull;

    for (int q0 = 0; q0 < QQ; q0 += 16){
        #pragma unroll
        for (int u = 0; u < 2; u++){
            int f = tid + u*256;
            {   // A tile: 128 c x 16 q, transpose + dup-pack
                int r = f >> 2, kk = (f & 3) << 2;
                float4 v = *(const float4*)(Sg + (size_t)r*QQ + q0 + kk);
                As2[kk+0][r] = pack2(v.x, v.x);
                As2[kk+1][r] = pack2(v.y, v.y);
                As2[kk+2][r] = pack2(v.z, v.z);
                As2[kk+3][r] = pack2(v.w, v.w);
            }
            {   // B tile: 16 q x 128 d, straight copy
                int k = f >> 5, dc = (f & 31) << 2;
                float4 v = *(const float4*)(Bg + (size_t)(q0 + k)*DD + dc);
                *(float4*)&Bs[k][dc] = v;
            }
        }
        __syncthreads();
        #pragma unroll
        for (int k = 0; k < 16; k++){
            unsigned long long a2[8];
            #pragma unroll
            for (int i = 0; i < 8; i++) a2[i] = As2[k][ty*8 + i];
            const ulonglong2* bp = reinterpret_cast<const ulonglong2*>(&Bs[k][tx*8]);
            ulonglong2 p0 = bp[0], p1 = bp[1];
            unsigned long long bf[4] = {p0.x, p0.y, p1.x, p1.y};
            #pragma unroll
            for (int i = 0; i < 8; i++)
                #pragma unroll
                for (int j = 0; j < 4; j++) ffma2(acc[i][j], a2[i], bf[j]);
        }
        __syncthreads();
    }

    // epilogue: out = [cont | c2q | cont*c2q | cont*c_dash]
    int dg = d0 + tx*8;
    float cd[8];
    #pragma unroll
    for (int j = 0; j < 8; j++) cd[j] = g_cdash[b*DD + dg + j];
    #pragma unroll
    for (int i = 0; i < 8; i++){
        int c = c0 + ty*8 + i;
        const float4* cp = (const float4*)(cont + ((size_t)b*CC + c)*DD + dg);
        float4 ct0 = cp[0], ct1 = cp[1];
        float s[8];
        #pragma unroll
        for (int j = 0; j < 4; j++) unpack2(acc[i][j], s[2*j], s[2*j+1]);
        float* orow = out + ((size_t)b*CC + c)*OD;
        *(float4*)(orow + dg)            = ct0;
        *(float4*)(orow + dg + 4)        = ct1;
        *(float4*)(orow + DD + dg)       = make_float4(s[0], s[1], s[2], s[3]);
        *(float4*)(orow + DD + dg + 4)   = make_float4(s[4], s[5], s[6], s[7]);
        *(float4*)(orow + 2*DD + dg)     = make_float4(ct0.x*s[0], ct0.y*s[1], ct0.z*s[2], ct0.w*s[3]);
        *(float4*)(orow + 2*DD + dg + 4) = make_float4(ct1.x*s[4], ct1.y*s[5], ct1.z*s[6], ct1.w*s[7]);
        *(float4*)(orow + 3*DD + dg)     = make_float4(ct0.x*cd[0], ct0.y*cd[1], ct0.z*cd[2], ct0.w*cd[3]);
        *(float4*)(orow + 3*DD + dg + 4) = make_float4(ct1.x*cd[4], ct1.y*cd[5], ct1.z*cd[6], ct1.w*cd[7]);
    }
}

// ---------------- launch ----------------
extern "C" void kernel_launch(void* const* d_in, const int* in_sizes, int n_in,
                              void* d_out, int out_size){
    const float* cont  = (const float*)d_in[0];
    const int*   cmask = (const int*)  d_in[1];
    const float* ques  = (const float*)d_in[2];
    const int*   qmask = (const int*)  d_in[3];
    const float* SW    = (const float*)d_in[4];
    float* out = (float*)d_out;

    k_rowdots<<<2560, 256>>>(cont, ques, SW);
    k_gemm1  <<<dim3(4, 32), 256>>>(cont, ques, SW);
    k_colpart<<<dim3(4, 32), 128>>>(qmask);
    k_colfinal<<<32, 128>>>();
    k_dist   <<<2048, 256>>>(qmask);
    k_cdd    <<<32, 512>>>(cmask);
    k_cdash  <<<dim3(6, 32), 128>>>(cont);
    k_gemm2  <<<dim3(6, 4, 32), 256>>>(cont, ques, out);
}